// round 3
// baseline (speedup 1.0000x reference)
#include <cuda_runtime.h>
#include <math.h>
#include <stdint.h>

// Problem constants
#define Bn   2
#define Tn   2048
#define HIDn 2048
#define Hn   16
#define DKn  128
#define DVn  128
#define KCn  4
#define BTn  (Bn*Tn)      // 4096
#define CHn  (Hn*DKn)     // 2048

// ---------------- scratch (static device globals; no allocation) ----------------
__device__ float g_xq[BTn*CHn];
__device__ float g_xk[BTn*CHn];
__device__ float g_xv[BTn*CHn];
__device__ float g_q [BTn*CHn];
__device__ float g_k [BTn*CHn];
__device__ float g_v [BTn*CHn];
__device__ float g_gd[BTn*CHn];   // decay gate g
__device__ float g_g2[BTn*CHn];   // output gate pre-sigmoid
__device__ float g_o [BTn*CHn];   // recurrence output / normed output
__device__ float g_t1[BTn*DVn];   // low-rank intermediate (4096x128)
__device__ float g_bt[BTn*Hn];    // beta (post-sigmoid)

// ---------------- fp32 SGEMM: C(MxN) = A(MxK) @ B(KxN), row-major ----------------
// Requires M%128==0, N%128==0, K%8==0 (true for all call sites).
__global__ __launch_bounds__(256) void sgemm128(
    int M, int N, int K,
    const float* __restrict__ A, const float* __restrict__ B, float* __restrict__ C)
{
    const int BM=128, BN=128, BK=8, TM=8, TN=8;
    __shared__ float As[BK][BM];
    __shared__ float Bs[BK][BN];

    int tid = threadIdx.x;
    int bx = blockIdx.x, by = blockIdx.y;
    const float* Ab = A + (size_t)by * BM * K;
    const float* Bb = B + (size_t)bx * BN;

    float acc[TM][TN];
    #pragma unroll
    for (int i = 0; i < TM; i++)
        #pragma unroll
        for (int j = 0; j < TN; j++) acc[i][j] = 0.f;

    int arow = tid >> 1;            // 0..127
    int acol = (tid & 1) << 2;      // 0 or 4
    int brow = tid >> 5;            // 0..7
    int bcol = (tid & 31) << 2;     // 0..124
    int trow = (tid >> 4) * TM;     // 0..120
    int tcol = (tid & 15) * TN;     // 0..120

    for (int k0 = 0; k0 < K; k0 += BK) {
        float4 av = *(const float4*)(Ab + (size_t)arow * K + k0 + acol);
        As[acol+0][arow] = av.x;
        As[acol+1][arow] = av.y;
        As[acol+2][arow] = av.z;
        As[acol+3][arow] = av.w;
        float4 bv = *(const float4*)(Bb + (size_t)(k0 + brow) * N + bcol);
        *(float4*)&Bs[brow][bcol] = bv;
        __syncthreads();

        #pragma unroll
        for (int kk = 0; kk < BK; kk++) {
            float a[TM], b[TN];
            #pragma unroll
            for (int i = 0; i < TM; i++) a[i] = As[kk][trow + i];
            #pragma unroll
            for (int j = 0; j < TN; j++) b[j] = Bs[kk][tcol + j];
            #pragma unroll
            for (int i = 0; i < TM; i++)
                #pragma unroll
                for (int j = 0; j < TN; j++)
                    acc[i][j] = fmaf(a[i], b[j], acc[i][j]);
        }
        __syncthreads();
    }

    float* Cb = C + (size_t)(by * BM) * N + bx * BN;
    #pragma unroll
    for (int i = 0; i < TM; i++)
        #pragma unroll
        for (int j = 0; j < TN; j += 4) {
            float4 v;
            v.x = acc[i][j+0]; v.y = acc[i][j+1]; v.z = acc[i][j+2]; v.w = acc[i][j+3];
            *(float4*)(Cb + (size_t)(trow + i) * N + tcol + j) = v;
        }
}

// ---------------- causal depthwise conv (KC=4) + silu ----------------
__global__ void conv_silu(const float* __restrict__ x, const float* __restrict__ w,
                          float* __restrict__ out)
{
    int idx = blockIdx.x * blockDim.x + threadIdx.x;
    if (idx >= BTn * CHn) return;
    int c  = idx % CHn;
    int bt = idx / CHn;
    int t  = bt % Tn;
    int b  = bt / Tn;
    float s = 0.f;
    #pragma unroll
    for (int i = 0; i < KCn; i++) {
        int tt = t - (KCn - 1) + i;
        if (tt >= 0)
            s = fmaf(x[((size_t)(b * Tn + tt)) * CHn + c], w[c * KCn + i], s);
    }
    out[idx] = s * (1.f / (1.f + expf(-s)));   // silu
}

// ---------------- decay gate: g = exp(-softplus(g + dt_bias) * exp(A_log[h])) ----------------
__global__ void gate_decay(float* __restrict__ g, const float* __restrict__ dtb,
                           const float* __restrict__ A_log)
{
    int idx = blockIdx.x * blockDim.x + threadIdx.x;
    if (idx >= BTn * CHn) return;
    int hd = idx & (CHn - 1);
    int h  = hd >> 7;            // /128
    float xv = g[idx] + dtb[hd];
    float sp = (xv > 20.f) ? xv : log1pf(expf(xv));
    g[idx] = expf(-sp * expf(A_log[h]));
}

// ---------------- beta = sigmoid(x @ Wb), N=16 skinny GEMM ----------------
__global__ __launch_bounds__(256) void beta_proj(
    const float* __restrict__ x, const float* __restrict__ Wb, float* __restrict__ beta)
{
    int warp = (blockIdx.x * blockDim.x + threadIdx.x) >> 5;
    int lane = threadIdx.x & 31;
    if (warp >= BTn) return;
    const float* xr = x + (size_t)warp * HIDn;
    float acc[Hn];
    #pragma unroll
    for (int n = 0; n < Hn; n++) acc[n] = 0.f;
    for (int k0 = lane; k0 < HIDn; k0 += 32) {
        float a = xr[k0];
        const float* br = Wb + (size_t)k0 * Hn;
        #pragma unroll
        for (int n = 0; n < Hn; n++) acc[n] = fmaf(a, br[n], acc[n]);
    }
    #pragma unroll
    for (int n = 0; n < Hn; n++) {
        #pragma unroll
        for (int o = 16; o; o >>= 1) acc[n] += __shfl_xor_sync(0xffffffffu, acc[n], o);
    }
    if (lane == 0) {
        #pragma unroll
        for (int n = 0; n < Hn; n++)
            beta[warp * Hn + n] = 1.f / (1.f + expf(-acc[n]));
    }
}

// ---------------- in-place L2 norm of q (with DK^-0.5 scale) and k ----------------
__global__ __launch_bounds__(256) void l2norm_qk(float* __restrict__ q, float* __restrict__ k)
{
    int warp = (blockIdx.x * blockDim.x + threadIdx.x) >> 5;
    int lane = threadIdx.x & 31;
    if (warp >= BTn * Hn) return;

    float4* qp = (float4*)(q + (size_t)warp * DKn);
    float4 v = qp[lane];
    float ss = v.x*v.x + v.y*v.y + v.z*v.z + v.w*v.w;
    #pragma unroll
    for (int o = 16; o; o >>= 1) ss += __shfl_xor_sync(0xffffffffu, ss, o);
    float r = rsqrtf(ss + 1e-6f) * 0.08838834764831845f;   // 1/sqrt(128)
    v.x *= r; v.y *= r; v.z *= r; v.w *= r;
    qp[lane] = v;

    float4* kp = (float4*)(k + (size_t)warp * DKn);
    float4 u = kp[lane];
    float sk = u.x*u.x + u.y*u.y + u.z*u.z + u.w*u.w;
    #pragma unroll
    for (int o = 16; o; o >>= 1) sk += __shfl_xor_sync(0xffffffffu, sk, o);
    float rk = rsqrtf(sk + 1e-6f);
    u.x *= rk; u.y *= rk; u.z *= rk; u.w *= rk;
    kp[lane] = u;
}

// ---------------- gated delta-rule recurrence ----------------
// grid (32, 4): blockIdx.x = b*H+h, blockIdx.y = v-column group (32 cols each)
// 128 threads: thread = j_local*4 + k_quarter; owns S[kq*32 .. kq*32+31][jbase+j_local]
__global__ __launch_bounds__(128) void recurrence(
    const float* __restrict__ q, const float* __restrict__ k, const float* __restrict__ v,
    const float* __restrict__ g, const float* __restrict__ beta, float* __restrict__ o)
{
    int bh = blockIdx.x;
    int b = bh >> 4, h = bh & 15;
    int jbase = blockIdx.y << 5;
    int tid = threadIdx.x;
    int jl  = tid >> 2;        // 0..31
    int kq  = tid & 3;         // 0..3
    int koff = kq << 5;        // 0,32,64,96

    __shared__ float sq[128], sk[128], sg[128], sv[32];
    __shared__ float sb;

    float S[32];
    #pragma unroll
    for (int i = 0; i < 32; i++) S[i] = 0.f;

    const size_t rowstride = (size_t)Hn * DKn;
    size_t base = ((size_t)b * Tn) * rowstride + (size_t)h * DKn;
    int bbase = (b * Tn) * Hn + h;

    for (int t = 0; t < Tn; t++, base += rowstride) {
        sq[tid] = q[base + tid];
        sk[tid] = k[base + tid];
        sg[tid] = g[base + tid];
        if (tid < 32) sv[tid] = v[base + jbase + tid];
        if (tid == 0) sb = beta[bbase + t * Hn];
        __syncthreads();

        float kreg[32];
        float partial = 0.f;
        #pragma unroll
        for (int i = 0; i < 32; i++) {
            float ki = sk[koff + i];
            kreg[i] = ki;
            S[i] *= sg[koff + i];
            partial = fmaf(ki, S[i], partial);
        }
        partial += __shfl_xor_sync(0xffffffffu, partial, 1);
        partial += __shfl_xor_sync(0xffffffffu, partial, 2);

        float delta = (sv[jl] - partial) * sb;

        float opart = 0.f;
        #pragma unroll
        for (int i = 0; i < 32; i++) {
            S[i] = fmaf(kreg[i], delta, S[i]);
            opart = fmaf(sq[koff + i], S[i], opart);
        }
        opart += __shfl_xor_sync(0xffffffffu, opart, 1);
        opart += __shfl_xor_sync(0xffffffffu, opart, 2);

        if (kq == 0) o[base + jbase + jl] = opart;
        __syncthreads();
    }
}

// ---------------- gated RMSNorm (in place on o) ----------------
__global__ __launch_bounds__(256) void rms_gate(
    float* __restrict__ o, const float* __restrict__ g2, const float* __restrict__ nw)
{
    int warp = (blockIdx.x * blockDim.x + threadIdx.x) >> 5;
    int lane = threadIdx.x & 31;
    if (warp >= BTn * Hn) return;

    float4* op = (float4*)(o + (size_t)warp * DVn);
    const float4* gp = (const float4*)(g2 + (size_t)warp * DVn);
    const float4* wp = (const float4*)nw;

    float4 v = op[lane];
    float ss = v.x*v.x + v.y*v.y + v.z*v.z + v.w*v.w;
    #pragma unroll
    for (int off = 16; off; off >>= 1) ss += __shfl_xor_sync(0xffffffffu, ss, off);
    float r = rsqrtf(ss * (1.f / 128.f) + 1e-6f);

    float4 w = wp[lane];
    float4 gg = gp[lane];
    float4 out;
    out.x = v.x * r * w.x * (1.f / (1.f + expf(-gg.x)));
    out.y = v.y * r * w.y * (1.f / (1.f + expf(-gg.y)));
    out.z = v.z * r * w.z * (1.f / (1.f + expf(-gg.z)));
    out.w = v.w * r * w.w * (1.f / (1.f + expf(-gg.w)));
    op[lane] = out;
}

// ---------------- launcher ----------------
extern "C" void kernel_launch(void* const* d_in, const int* in_sizes, int n_in,
                              void* d_out, int out_size)
{
    const float* x     = (const float*)d_in[0];
    const float* Wq    = (const float*)d_in[1];
    const float* Wk    = (const float*)d_in[2];
    const float* Wv    = (const float*)d_in[3];
    const float* convq = (const float*)d_in[4];
    const float* convk = (const float*)d_in[5];
    const float* convv = (const float*)d_in[6];
    const float* A_log = (const float*)d_in[7];
    const float* Wfa   = (const float*)d_in[8];
    const float* Wfb   = (const float*)d_in[9];
    const float* dtb   = (const float*)d_in[10];
    const float* Wb    = (const float*)d_in[11];
    const float* Wga   = (const float*)d_in[12];
    const float* Wgb   = (const float*)d_in[13];
    const float* nw    = (const float*)d_in[14];
    const float* Wo    = (const float*)d_in[15];

    float *xq, *xk, *xv, *q, *k, *v, *gd, *g2b, *ob, *t1, *bt;
    cudaGetSymbolAddress((void**)&xq,  g_xq);
    cudaGetSymbolAddress((void**)&xk,  g_xk);
    cudaGetSymbolAddress((void**)&xv,  g_xv);
    cudaGetSymbolAddress((void**)&q,   g_q);
    cudaGetSymbolAddress((void**)&k,   g_k);
    cudaGetSymbolAddress((void**)&v,   g_v);
    cudaGetSymbolAddress((void**)&gd,  g_gd);
    cudaGetSymbolAddress((void**)&g2b, g_g2);
    cudaGetSymbolAddress((void**)&ob,  g_o);
    cudaGetSymbolAddress((void**)&t1,  g_t1);
    cudaGetSymbolAddress((void**)&bt,  g_bt);

    dim3 gBig(CHn / 128, BTn / 128);      // (16, 32)
    dim3 gNarrow(1, BTn / 128);           // (1, 32)
    int  tot = BTn * CHn;
    int  eb  = (tot + 255) / 256;

    // input projections
    sgemm128<<<gBig, 256>>>(BTn, CHn, HIDn, x, Wq, xq);
    sgemm128<<<gBig, 256>>>(BTn, CHn, HIDn, x, Wk, xk);
    sgemm128<<<gBig, 256>>>(BTn, CHn, HIDn, x, Wv, xv);

    // causal conv + silu
    conv_silu<<<eb, 256>>>(xq, convq, q);
    conv_silu<<<eb, 256>>>(xk, convk, k);
    conv_silu<<<eb, 256>>>(xv, convv, v);

    // decay gate (low-rank)
    sgemm128<<<gNarrow, 256>>>(BTn, DVn, HIDn, x, Wfa, t1);
    sgemm128<<<gBig, 256>>>(BTn, CHn, DVn, t1, Wfb, gd);
    gate_decay<<<eb, 256>>>(gd, dtb, A_log);

    // beta
    beta_proj<<<(BTn * 32 + 255) / 256, 256>>>(x, Wb, bt);

    // output gate (low-rank), pre-sigmoid kept in g2b
    sgemm128<<<gNarrow, 256>>>(BTn, DVn, HIDn, x, Wga, t1);
    sgemm128<<<gBig, 256>>>(BTn, CHn, DVn, t1, Wgb, g2b);

    // L2 normalize q (scaled) and k in place
    l2norm_qk<<<(BTn * Hn) / 8, 256>>>(q, k);

    // sequential gated delta-rule scan
    recurrence<<<dim3(Bn * Hn, 4), 128>>>(q, k, v, gd, bt, ob);

    // gated RMSNorm in place
    rms_gate<<<(BTn * Hn) / 8, 256>>>(ob, g2b, nw);

    // output projection
    sgemm128<<<gBig, 256>>>(BTn, CHn, CHn, ob, Wo, (float*)d_out);
}